// round 1
// baseline (speedup 1.0000x reference)
#include <cuda_runtime.h>
#include <cstdint>

#define T_STEPS 512
#define B_SZ 32
#define D_SZ 1024
#define H_SZ 1024
#define G3 3072              // 3*H
#define NBLK 128             // recurrent blocks (<=148 SMs, 1 per SM)
#define COLS_PER_BLK 8       // H columns per block (128*8 = 1024)
#define RTHREADS 256
#define HS_STRIDE 1028       // 1024 + 4 pad: conflict-free LDS.128, keeps 16B align

// -------------------- device scratch (no allocs allowed) --------------------
__device__ float g_gi[(size_t)T_STEPS * G3 * B_SZ];   // [(t*3072 + n)*32 + b]
__device__ float g_wp[3 * H_SZ * D_SZ];               // [(g*H + c)*K + k] k-contiguous
__device__ float g_h[2][B_SZ * H_SZ];                 // ping-pong h state
__device__ unsigned g_bar;                            // monotonic barrier counter

// -------------------- f32x2 helpers (FFMA2: 2x fp32 throughput) -------------
__device__ __forceinline__ unsigned long long ffma2(unsigned long long a,
                                                    unsigned long long b,
                                                    unsigned long long c) {
    unsigned long long d;
    asm("fma.rn.f32x2 %0, %1, %2, %3;" : "=l"(d) : "l"(a), "l"(b), "l"(c));
    return d;
}
__device__ __forceinline__ float f2lo(unsigned long long v) {
    return __uint_as_float((unsigned)(v & 0xFFFFFFFFull));
}
__device__ __forceinline__ float f2hi(unsigned long long v) {
    return __uint_as_float((unsigned)(v >> 32));
}

// -------------------- init: pack W_hh + zero h state -------------------------
// g_wp[(g*H + c)*K + k] = W_hh[k*3H + g*H + c]   (gc = g*H + c = o>>10)
__global__ void pack_kernel(const float* __restrict__ W_hh) {
    int o = blockIdx.x * blockDim.x + threadIdx.x;
    if (o < 3 * H_SZ * D_SZ) {
        int k  = o & (D_SZ - 1);
        int gc = o >> 10;
        g_wp[o] = W_hh[(size_t)k * G3 + gc];
    }
    if (o < 2 * B_SZ * H_SZ) {
        ((float*)g_h)[o] = 0.0f;
    }
}

// -------------------- pre-GEMM: gi = X @ W_ih + b_ih ------------------------
// M=16384 (t,b), N=3072, K=1024. 64x64 tile, 256 thr, 4x4 microtile, FFMA2.
// Output written in [t][n][b] packed layout for coalesced recurrent reads.
__global__ void __launch_bounds__(256)
pregemm_kernel(const float* __restrict__ X, const float* __restrict__ W,
               const float* __restrict__ bias) {
    __shared__ float As[16][64];   // As[k][m]
    __shared__ float Bs[16][64];   // Bs[k][n]
    int tid = threadIdx.x;
    int m0 = blockIdx.y * 64;
    int n0 = blockIdx.x * 64;
    int ty = tid >> 4, tx = tid & 15;

    unsigned long long acc[4][2];
#pragma unroll
    for (int i = 0; i < 4; i++) { acc[i][0] = 0ull; acc[i][1] = 0ull; }

    int rowA = tid >> 2, kqA = (tid & 3) * 4;   // X loader
    int rowB = tid >> 4, cqB = (tid & 15) * 4;  // W loader

    for (int k0 = 0; k0 < D_SZ; k0 += 16) {
        float4 xv = *(const float4*)(X + (size_t)(m0 + rowA) * D_SZ + k0 + kqA);
        As[kqA + 0][rowA] = xv.x;
        As[kqA + 1][rowA] = xv.y;
        As[kqA + 2][rowA] = xv.z;
        As[kqA + 3][rowA] = xv.w;
        *(float4*)&Bs[rowB][cqB] =
            *(const float4*)(W + (size_t)(k0 + rowB) * G3 + n0 + cqB);
        __syncthreads();
#pragma unroll
        for (int k = 0; k < 16; k++) {
            float4 a = *(const float4*)&As[k][ty * 4];
            ulonglong2 b2 = *(const ulonglong2*)&Bs[k][tx * 4];
            unsigned long long ad0, ad1, ad2, ad3;
            asm("mov.b64 %0, {%1,%1};" : "=l"(ad0) : "f"(a.x));
            asm("mov.b64 %0, {%1,%1};" : "=l"(ad1) : "f"(a.y));
            asm("mov.b64 %0, {%1,%1};" : "=l"(ad2) : "f"(a.z));
            asm("mov.b64 %0, {%1,%1};" : "=l"(ad3) : "f"(a.w));
            acc[0][0] = ffma2(ad0, b2.x, acc[0][0]);
            acc[0][1] = ffma2(ad0, b2.y, acc[0][1]);
            acc[1][0] = ffma2(ad1, b2.x, acc[1][0]);
            acc[1][1] = ffma2(ad1, b2.y, acc[1][1]);
            acc[2][0] = ffma2(ad2, b2.x, acc[2][0]);
            acc[2][1] = ffma2(ad2, b2.y, acc[2][1]);
            acc[3][0] = ffma2(ad3, b2.x, acc[3][0]);
            acc[3][1] = ffma2(ad3, b2.y, acc[3][1]);
        }
        __syncthreads();
    }

#pragma unroll
    for (int i = 0; i < 4; i++) {
        int m = m0 + ty * 4 + i;
        int t = m >> 5, b = m & 31;
#pragma unroll
        for (int j = 0; j < 2; j++) {
            int n = n0 + tx * 4 + j * 2;
            float v0 = f2lo(acc[i][j]) + bias[n];
            float v1 = f2hi(acc[i][j]) + bias[n + 1];
            size_t base = ((size_t)t * G3 + n) * B_SZ + b;
            g_gi[base] = v0;
            g_gi[base + B_SZ] = v1;   // n+1 -> +32 in packed layout
        }
    }
}

// -------------------- grid barrier (monotonic, wrap-safe) -------------------
__device__ __forceinline__ void grid_barrier() {
    __syncthreads();
    if (threadIdx.x == 0) {
        __threadfence();
        unsigned my = atomicAdd(&g_bar, 1u);
        unsigned target = my - (my % NBLK) + NBLK;
        unsigned v;
        do {
            asm volatile("ld.acquire.gpu.b32 %0, [%1];"
                         : "=r"(v) : "l"(&g_bar) : "memory");
            if ((int)(v - target) >= 0) break;
            __nanosleep(32);
        } while (true);
    }
    __syncthreads();
}

// -------------------- persistent recurrent kernel ---------------------------
// 128 blocks x 256 thr. Block owns 8 H-columns; warp = 1 column (3 gates),
// lane = batch row. W packed k-contiguous -> uniform LDG.128 (L1-resident,
// persists across steps in-kernel). h staged in SMEM, read via __ldcg.
extern __shared__ float smem_rnn[];
__global__ void __launch_bounds__(RTHREADS, 1)
rnn_kernel(const float* __restrict__ paddings, const float* __restrict__ b_hh,
           float* __restrict__ out, int out_size) {
    float* hs  = smem_rnn;                        // [32][1028]
    float* hst = smem_rnn + 32 * HS_STRIDE;       // [32][8] staged h_new

    int tid  = threadIdx.x;
    int warp = tid >> 5, lane = tid & 31;
    int c = blockIdx.x * COLS_PER_BLK + warp;     // H column
    int b = lane;                                 // batch row

    const float* wr = g_wp + (size_t)(0 * H_SZ + c) * D_SZ;
    const float* wz = g_wp + (size_t)(1 * H_SZ + c) * D_SZ;
    const float* wn = g_wp + (size_t)(2 * H_SZ + c) * D_SZ;
    float bh_r = b_hh[c], bh_z = b_hh[H_SZ + c], bh_n = b_hh[2 * H_SZ + c];

    const bool has_tail =
        (size_t)out_size >= (size_t)T_STEPS * B_SZ * H_SZ + 2u * B_SZ * H_SZ;

    for (int t = 0; t < T_STEPS; t++) {
        const float* hcur = g_h[t & 1];
        // ---- load h -> SMEM (L2 reads via .cg; avoids stale L1) ----
#pragma unroll
        for (int i = 0; i < 32; i++) {
            int idx4 = i * RTHREADS + tid;
            float4 v = __ldcg((const float4*)hcur + idx4);
            int bb = idx4 >> 8;
            int kk = (idx4 & 255) << 2;
            *(float4*)&hs[bb * HS_STRIDE + kk] = v;
        }
        __syncthreads();

        // ---- 3 gate dots over K=1024 with FFMA2 ----
        unsigned long long a0 = 0, a1 = 0, z0 = 0, z1 = 0, n0 = 0, n1 = 0;
        const float* hrow = hs + b * HS_STRIDE;
#pragma unroll 4
        for (int k = 0; k < D_SZ; k += 4) {
            ulonglong2 h2 = *(const ulonglong2*)(hrow + k);
            ulonglong2 r2 = *(const ulonglong2*)(wr + k);
            ulonglong2 q2 = *(const ulonglong2*)(wz + k);
            ulonglong2 n2 = *(const ulonglong2*)(wn + k);
            a0 = ffma2(h2.x, r2.x, a0);
            a1 = ffma2(h2.y, r2.y, a1);
            z0 = ffma2(h2.x, q2.x, z0);
            z1 = ffma2(h2.y, q2.y, z1);
            n0 = ffma2(h2.x, n2.x, n0);
            n1 = ffma2(h2.y, n2.y, n1);
        }
        float ar = f2lo(a0) + f2hi(a0) + f2lo(a1) + f2hi(a1) + bh_r;
        float az = f2lo(z0) + f2hi(z0) + f2lo(z1) + f2hi(z1) + bh_z;
        float an = f2lo(n0) + f2hi(n0) + f2lo(n1) + f2hi(n1) + bh_n;

        size_t gbase = ((size_t)t * G3 + c) * B_SZ + b;   // coalesced: lane = b
        float ir  = g_gi[gbase];
        float iz  = g_gi[gbase + (size_t)H_SZ * B_SZ];
        float in_ = g_gi[gbase + (size_t)2 * H_SZ * B_SZ];

        float r  = 1.0f / (1.0f + __expf(-(ir + ar)));
        float z  = 1.0f / (1.0f + __expf(-(iz + az)));
        float nn = tanhf(in_ + r * an);
        float hp = hrow[c];
        float hn = (1.0f - z) * nn + z * hp;
        float p  = paddings[t * B_SZ + b];
        hn = p * hp + (1.0f - p) * hn;

        hst[b * COLS_PER_BLK + warp] = hn;
        __syncthreads();

        // ---- coalesced write of h_new to state + output ----
        {
            int b2 = tid >> 3, cl = tid & 7;
            float v = hst[b2 * COLS_PER_BLK + cl];
            int cg = blockIdx.x * COLS_PER_BLK + cl;
            float* hnext = g_h[(t + 1) & 1];
            hnext[b2 * H_SZ + cg] = v;
            out[(size_t)t * B_SZ * H_SZ + b2 * H_SZ + cg] = v;
            if (t == T_STEPS - 1 && has_tail) {
                size_t tail = (size_t)T_STEPS * B_SZ * H_SZ;
                out[tail + b2 * H_SZ + cg] = v;                    // outputs[-1]
                out[tail + (size_t)B_SZ * H_SZ + b2 * H_SZ + cg] = v;  // h_last
            }
        }
        grid_barrier();
    }
}

// -------------------- launch ------------------------------------------------
extern "C" void kernel_launch(void* const* d_in, const int* in_sizes, int n_in,
                              void* d_out, int out_size) {
    const float* X        = (const float*)d_in[0];  // [T,B,D]
    const float* paddings = (const float*)d_in[1];  // [T,B,1]
    const float* W_ih     = (const float*)d_in[2];  // [D,3H]
    const float* W_hh     = (const float*)d_in[3];  // [H,3H]
    const float* b_ih     = (const float*)d_in[4];  // [3H]
    const float* b_hh     = (const float*)d_in[5];  // [3H]
    float* out = (float*)d_out;

    (void)in_sizes; (void)n_in;

    // 1) pack W_hh (k-contiguous per gate column) + zero h state
    pack_kernel<<<(3 * H_SZ * D_SZ + 255) / 256, 256>>>(W_hh);

    // 2) gi = X @ W_ih + b_ih for all timesteps (one big GEMM)
    dim3 gg(G3 / 64, (T_STEPS * B_SZ) / 64);
    pregemm_kernel<<<gg, 256>>>(X, W_ih, b_ih);

    // 3) persistent recurrence
    int smem_bytes = (32 * HS_STRIDE + 32 * COLS_PER_BLK) * (int)sizeof(float);
    cudaFuncSetAttribute(rnn_kernel,
                         cudaFuncAttributeMaxDynamicSharedMemorySize, smem_bytes);
    rnn_kernel<<<NBLK, RTHREADS, smem_bytes>>>(paddings, b_hh, out, out_size);
}

// round 3
// speedup vs baseline: 1.9604x; 1.9604x over previous
#include <cuda_runtime.h>
#include <cstdint>

#define T_STEPS 512
#define B_SZ 32
#define D_SZ 1024
#define H_SZ 1024
#define G3 3072
#define NBLK 128             // recurrent blocks, 1/SM, single wave
#define RTHREADS 256

typedef unsigned long long u64;

// -------------------- device scratch --------------------
__device__ float g_gi[(size_t)T_STEPS * B_SZ * G3];     // [m=t*32+b][3072] natural
__device__ float g_wtb[(size_t)NBLK * D_SZ * 24];       // [bx][k][cg] cg=g*8+ci
__device__ float g_ht[2][H_SZ * B_SZ];                  // transposed h: [k][b]
__device__ unsigned g_bar;

// -------------------- f32x2 helpers --------------------
__device__ __forceinline__ u64 ffma2(u64 a, u64 b, u64 c) {
    u64 d; asm("fma.rn.f32x2 %0, %1, %2, %3;" : "=l"(d) : "l"(a), "l"(b), "l"(c));
    return d;
}
__device__ __forceinline__ u64 addf2(u64 a, u64 b) {
    u64 d; asm("add.rn.f32x2 %0, %1, %2;" : "=l"(d) : "l"(a), "l"(b));
    return d;
}
__device__ __forceinline__ u64 dup2(float x) {
    u64 d; asm("mov.b64 %0, {%1,%1};" : "=l"(d) : "f"(x));
    return d;
}
__device__ __forceinline__ float f2lo(u64 v) { return __uint_as_float((unsigned)v); }
__device__ __forceinline__ float f2hi(u64 v) { return __uint_as_float((unsigned)(v >> 32)); }

// -------------------- pack: W_hh -> per-block [k][24] + zero ht ------------
__global__ void pack_kernel(const float* __restrict__ W_hh) {
    int o = blockIdx.x * blockDim.x + threadIdx.x;
    if (o < NBLK * D_SZ * 24) {
        int bx = o / (D_SZ * 24);
        int r  = o - bx * (D_SZ * 24);
        int k  = r / 24;
        int j  = r - k * 24;
        int g  = j >> 3, ci = j & 7;
        g_wtb[o] = W_hh[(size_t)k * G3 + g * H_SZ + bx * 8 + ci];
    }
    if (o < 2 * H_SZ * B_SZ) ((float*)g_ht)[o] = 0.0f;
}

// -------------------- pre-GEMM: gi = X @ W_ih + b_ih -----------------------
// 128x128 tile, 256 thr, 8x8 microtile (m-paired f32x2), double-buffered smem.
// As row stride 132 floats = 528B: 16B-aligned vector reads AND conflict-free
// scalar stores (banks {rowA, rowA+16}).
__global__ void __launch_bounds__(256, 1)
pregemm_kernel(const float* __restrict__ X, const float* __restrict__ W,
               const float* __restrict__ bias) {
    __shared__ float As[2][8][132];   // [k][m], padded (528B row, 16B aligned)
    __shared__ float Bs[2][8][128];   // [k][n]
    int tid = threadIdx.x;
    int n0 = blockIdx.x * 128;
    int m0 = blockIdx.y * 128;
    int tx = tid & 15, ty = tid >> 4;

    int rowA = tid >> 1, kqA = (tid & 1) * 4;
    int rowB = tid >> 5, nqB = (tid & 31) * 4;

    u64 acc[4][8];
#pragma unroll
    for (int j = 0; j < 4; j++)
#pragma unroll
        for (int n = 0; n < 8; n++) acc[j][n] = 0ull;

    // preload tile 0
    float4 xv = *(const float4*)(X + (size_t)(m0 + rowA) * D_SZ + kqA);
    float4 wv = *(const float4*)(W + (size_t)rowB * G3 + n0 + nqB);
    As[0][kqA + 0][rowA] = xv.x; As[0][kqA + 1][rowA] = xv.y;
    As[0][kqA + 2][rowA] = xv.z; As[0][kqA + 3][rowA] = xv.w;
    *(float4*)&Bs[0][rowB][nqB] = wv;
    __syncthreads();

    int buf = 0;
    const int NT = D_SZ / 8;
    for (int tile = 0; tile < NT; tile++) {
        float4 xn, wn;
        if (tile + 1 < NT) {
            int k0 = (tile + 1) * 8;
            xn = *(const float4*)(X + (size_t)(m0 + rowA) * D_SZ + k0 + kqA);
            wn = *(const float4*)(W + (size_t)(k0 + rowB) * G3 + n0 + nqB);
        }
#pragma unroll
        for (int k = 0; k < 8; k++) {
            ulonglong2 A0 = *(const ulonglong2*)&As[buf][k][ty * 8];
            ulonglong2 A1 = *(const ulonglong2*)&As[buf][k][ty * 8 + 4];
            float4 b0 = *(const float4*)&Bs[buf][k][tx * 8];
            float4 b1 = *(const float4*)&Bs[buf][k][tx * 8 + 4];
            u64 bd[8];
            bd[0] = dup2(b0.x); bd[1] = dup2(b0.y); bd[2] = dup2(b0.z); bd[3] = dup2(b0.w);
            bd[4] = dup2(b1.x); bd[5] = dup2(b1.y); bd[6] = dup2(b1.z); bd[7] = dup2(b1.w);
            u64 a2[4] = {A0.x, A0.y, A1.x, A1.y};
#pragma unroll
            for (int j = 0; j < 4; j++)
#pragma unroll
                for (int n = 0; n < 8; n++)
                    acc[j][n] = ffma2(a2[j], bd[n], acc[j][n]);
        }
        if (tile + 1 < NT) {
            int nb = buf ^ 1;
            As[nb][kqA + 0][rowA] = xn.x; As[nb][kqA + 1][rowA] = xn.y;
            As[nb][kqA + 2][rowA] = xn.z; As[nb][kqA + 3][rowA] = xn.w;
            *(float4*)&Bs[nb][rowB][nqB] = wn;
            __syncthreads();
            buf = nb;
        }
    }

    float4 bb0 = *(const float4*)(bias + n0 + tx * 8);
    float4 bb1 = *(const float4*)(bias + n0 + tx * 8 + 4);
    float bb[8] = {bb0.x, bb0.y, bb0.z, bb0.w, bb1.x, bb1.y, bb1.z, bb1.w};
#pragma unroll
    for (int j = 0; j < 4; j++) {
        int me = m0 + ty * 8 + 2 * j;
        float4 lo0, lo1, hi0, hi1;
        lo0.x = f2lo(acc[j][0]) + bb[0]; lo0.y = f2lo(acc[j][1]) + bb[1];
        lo0.z = f2lo(acc[j][2]) + bb[2]; lo0.w = f2lo(acc[j][3]) + bb[3];
        lo1.x = f2lo(acc[j][4]) + bb[4]; lo1.y = f2lo(acc[j][5]) + bb[5];
        lo1.z = f2lo(acc[j][6]) + bb[6]; lo1.w = f2lo(acc[j][7]) + bb[7];
        hi0.x = f2hi(acc[j][0]) + bb[0]; hi0.y = f2hi(acc[j][1]) + bb[1];
        hi0.z = f2hi(acc[j][2]) + bb[2]; hi0.w = f2hi(acc[j][3]) + bb[3];
        hi1.x = f2hi(acc[j][4]) + bb[4]; hi1.y = f2hi(acc[j][5]) + bb[5];
        hi1.z = f2hi(acc[j][6]) + bb[6]; hi1.w = f2hi(acc[j][7]) + bb[7];
        float* p0 = g_gi + (size_t)me * G3 + n0 + tx * 8;
        float* p1 = p0 + G3;
        *(float4*)p0 = lo0; *(float4*)(p0 + 4) = lo1;
        *(float4*)p1 = hi0; *(float4*)(p1 + 4) = hi1;
    }
}

// -------------------- grid barrier --------------------
__device__ __forceinline__ void grid_barrier() {
    __syncthreads();
    if (threadIdx.x == 0) {
        __threadfence();
        unsigned my = atomicAdd(&g_bar, 1u);
        unsigned target = my - (my % NBLK) + NBLK;
        unsigned v;
        do {
            asm volatile("ld.acquire.gpu.b32 %0, [%1];"
                         : "=r"(v) : "l"(&g_bar) : "memory");
            if ((int)(v - target) >= 0) break;
        } while (true);
    }
    __syncthreads();
}

// -------------------- persistent recurrent kernel ---------------------------
// 128 blocks x 256 thr. Block owns 8 H cols (24 gate-cols). Warp w handles
// k in [128w,128w+128) for ALL 24 gate-cols; lane = batch b (h scalar per k,
// duplicated to f32x2; weights as pairs from SMEM). Reduce 8 partials in SMEM.
extern __shared__ unsigned char smem_raw[];
__global__ void __launch_bounds__(RTHREADS, 1)
rnn_kernel(const float* __restrict__ paddings, const float* __restrict__ b_hh,
           float* __restrict__ out, int out_size) {
    float* sw   = (float*)smem_raw;                    // [1024][24]  96KB
    u64*   sred = (u64*)(smem_raw + 98304);            // [8*12][32]  24KB
    float* sout = (float*)(smem_raw + 98304 + 24576);  // [32][9]

    int tid = threadIdx.x;
    int warp = tid >> 5, lane = tid & 31;
    int bx = blockIdx.x;
    int ci = tid >> 5;            // gate-stage column within block (reuse warp id)
    int b  = lane;
    int c  = bx * 8 + ci;

    // load this block's weights into smem (once)
    {
        const float4* src = (const float4*)(g_wtb + (size_t)bx * D_SZ * 24);
        float4* dst = (float4*)sw;
#pragma unroll
        for (int i = 0; i < 24; i++) dst[i * RTHREADS + tid] = src[i * RTHREADS + tid];
    }
    float bh_r = b_hh[c], bh_z = b_hh[H_SZ + c], bh_n = b_hh[2 * H_SZ + c];
    __syncthreads();

    const bool has_tail =
        (size_t)out_size >= (size_t)T_STEPS * B_SZ * H_SZ + 2u * B_SZ * H_SZ;
    int kb = warp * 128;

    for (int t = 0; t < T_STEPS; t++) {
        const float* ht = g_ht[t & 1];
        // prefetch gate-stage operands (latency hidden under dot loop)
        size_t gm = (size_t)(t * B_SZ + b) * G3 + c;
        float ir  = __ldg(&g_gi[gm]);
        float iz  = __ldg(&g_gi[gm + H_SZ]);
        float in_ = __ldg(&g_gi[gm + 2 * H_SZ]);
        float p   = __ldg(&paddings[t * B_SZ + b]);
        float hp  = __ldcg(&ht[c * B_SZ + b]);

        // ---- dot: 24 gate-cols x k-slice of 128, all 32 b in parallel ----
        u64 acc[12];
#pragma unroll
        for (int j = 0; j < 12; j++) acc[j] = 0ull;

        const float* hcol = ht + lane;
        float hbuf[8];
#pragma unroll
        for (int u = 0; u < 8; u++) hbuf[u] = __ldcg(hcol + (kb + u) * B_SZ);

        for (int kk = 0; kk < 128; kk += 8) {
            float hnx[8] = {0, 0, 0, 0, 0, 0, 0, 0};
            if (kk < 120) {
#pragma unroll
                for (int u = 0; u < 8; u++)
                    hnx[u] = __ldcg(hcol + (kb + kk + 8 + u) * B_SZ);
            }
#pragma unroll
            for (int u = 0; u < 8; u++) {
                int k = kb + kk + u;
                u64 h2 = dup2(hbuf[u]);
                const ulonglong2* wr = (const ulonglong2*)(sw + k * 24);
                ulonglong2 w0 = wr[0], w1 = wr[1], w2 = wr[2];
                ulonglong2 w3 = wr[3], w4 = wr[4], w5 = wr[5];
                acc[0]  = ffma2(h2, w0.x, acc[0]);
                acc[1]  = ffma2(h2, w0.y, acc[1]);
                acc[2]  = ffma2(h2, w1.x, acc[2]);
                acc[3]  = ffma2(h2, w1.y, acc[3]);
                acc[4]  = ffma2(h2, w2.x, acc[4]);
                acc[5]  = ffma2(h2, w2.y, acc[5]);
                acc[6]  = ffma2(h2, w3.x, acc[6]);
                acc[7]  = ffma2(h2, w3.y, acc[7]);
                acc[8]  = ffma2(h2, w4.x, acc[8]);
                acc[9]  = ffma2(h2, w4.y, acc[9]);
                acc[10] = ffma2(h2, w5.x, acc[10]);
                acc[11] = ffma2(h2, w5.y, acc[11]);
            }
#pragma unroll
            for (int u = 0; u < 8; u++) hbuf[u] = hnx[u];
        }

        // ---- store partials [w][j][b] ----
#pragma unroll
        for (int j = 0; j < 12; j++)
            sred[(warp * 12 + j) * B_SZ + lane] = acc[j];
        __syncthreads();

        // ---- reduce 8 partials + gate math (thread = (b, ci)) ----
        int jr = ci >> 1;
        u64 pr = 0, pz = 0, pn = 0;
#pragma unroll
        for (int w = 0; w < 8; w++) {
            const u64* base = sred + (size_t)w * 12 * B_SZ;
            pr = addf2(pr, base[jr * B_SZ + b]);
            pz = addf2(pz, base[(4 + jr) * B_SZ + b]);
            pn = addf2(pn, base[(8 + jr) * B_SZ + b]);
        }
        int hi = ci & 1;
        float ar = (hi ? f2hi(pr) : f2lo(pr)) + bh_r;
        float az = (hi ? f2hi(pz) : f2lo(pz)) + bh_z;
        float an = (hi ? f2hi(pn) : f2lo(pn)) + bh_n;

        float r  = 1.0f / (1.0f + __expf(-(ir + ar)));
        float z  = 1.0f / (1.0f + __expf(-(iz + az)));
        float nn = tanhf(in_ + r * an);
        float hn = (1.0f - z) * nn + z * hp;
        hn = p * hp + (1.0f - p) * hn;

        g_ht[(t + 1) & 1][c * B_SZ + b] = hn;   // coalesced (lanes = b)
        sout[b * 9 + ci] = hn;
        __syncthreads();

        // ---- coalesced [b][c] output write ----
        {
            int b2 = tid >> 3, cl = tid & 7;
            float v = sout[b2 * 9 + cl];
            int cg = bx * 8 + cl;
            out[(size_t)t * B_SZ * H_SZ + b2 * H_SZ + cg] = v;
            if (t == T_STEPS - 1 && has_tail) {
                size_t tail = (size_t)T_STEPS * B_SZ * H_SZ;
                out[tail + b2 * H_SZ + cg] = v;
                out[tail + (size_t)B_SZ * H_SZ + b2 * H_SZ + cg] = v;
            }
        }
        grid_barrier();
    }
}

// -------------------- launch --------------------
extern "C" void kernel_launch(void* const* d_in, const int* in_sizes, int n_in,
                              void* d_out, int out_size) {
    const float* X        = (const float*)d_in[0];
    const float* paddings = (const float*)d_in[1];
    const float* W_ih     = (const float*)d_in[2];
    const float* W_hh     = (const float*)d_in[3];
    const float* b_ih     = (const float*)d_in[4];
    const float* b_hh     = (const float*)d_in[5];
    float* out = (float*)d_out;
    (void)in_sizes; (void)n_in;

    pack_kernel<<<(NBLK * D_SZ * 24 + 255) / 256, 256>>>(W_hh);

    dim3 gg(G3 / 128, (T_STEPS * B_SZ) / 128);
    pregemm_kernel<<<gg, 256>>>(X, W_ih, b_ih);

    int smem_bytes = 98304 + 24576 + 32 * 9 * (int)sizeof(float);
    cudaFuncSetAttribute(rnn_kernel,
                         cudaFuncAttributeMaxDynamicSharedMemorySize, smem_bytes);
    rnn_kernel<<<NBLK, RTHREADS, smem_bytes>>>(paddings, b_hh, out, out_size);
}

// round 5
// speedup vs baseline: 2.4764x; 1.2632x over previous
#include <cuda_runtime.h>
#include <cuda_bf16.h>
#include <cstdint>

#define T_STEPS 512
#define B_SZ 32
#define D_SZ 1024
#define H_SZ 1024
#define G3 3072
#define KEXT 3072            // 3*D extended-K for bf16 split GEMM
#define NBLK 128
#define RTHREADS 256
#define NCHUNK (KEXT / 64)   // 48 K-chunks of 64 bf16

typedef unsigned long long u64;

// -------------------- device scratch --------------------
__device__ float g_gi[(size_t)T_STEPS * B_SZ * G3];             // [m][3072] fp32
__device__ __nv_bfloat16 g_aext[(size_t)T_STEPS * B_SZ * KEXT]; // [m][kext]
__device__ __nv_bfloat16 g_bext[(size_t)G3 * KEXT];             // [n][kext]
__device__ float g_wtb[(size_t)NBLK * D_SZ * 24];
__device__ float g_ht[2][H_SZ * B_SZ];
__device__ unsigned g_bar;

// -------------------- f32x2 helpers --------------------
__device__ __forceinline__ u64 ffma2(u64 a, u64 b, u64 c) {
    u64 d; asm("fma.rn.f32x2 %0, %1, %2, %3;" : "=l"(d) : "l"(a), "l"(b), "l"(c));
    return d;
}
__device__ __forceinline__ u64 addf2(u64 a, u64 b) {
    u64 d; asm("add.rn.f32x2 %0, %1, %2;" : "=l"(d) : "l"(a), "l"(b));
    return d;
}
__device__ __forceinline__ u64 dup2(float x) {
    u64 d; asm("mov.b64 %0, {%1,%1};" : "=l"(d) : "f"(x));
    return d;
}
__device__ __forceinline__ float f2lo(u64 v) { return __uint_as_float((unsigned)v); }
__device__ __forceinline__ float f2hi(u64 v) { return __uint_as_float((unsigned)(v >> 32)); }

// -------------------- smem / mma helpers (base-target ISA only) -------------
__device__ __forceinline__ uint32_t smem_u32(const void* p) {
    uint32_t a;
    asm("{ .reg .u64 t; cvta.to.shared.u64 t, %1; cvt.u32.u64 %0, t; }"
        : "=r"(a) : "l"(p));
    return a;
}
#define SW128(off) ((off) ^ (((off) >> 3) & 0x70))

__device__ __forceinline__ void cp16(uint32_t sm, const void* g) {
    asm volatile("cp.async.cg.shared.global [%0], [%1], 16;" :: "r"(sm), "l"(g));
}
#define CP_COMMIT() asm volatile("cp.async.commit_group;" ::: "memory")
#define CP_WAIT(n)  asm volatile("cp.async.wait_group %0;" :: "n"(n) : "memory")

__device__ __forceinline__ void ldm_x4(uint32_t* r, uint32_t addr) {
    asm volatile("ldmatrix.sync.aligned.m8n8.x4.shared.b16 {%0,%1,%2,%3}, [%4];"
                 : "=r"(r[0]), "=r"(r[1]), "=r"(r[2]), "=r"(r[3]) : "r"(addr));
}
__device__ __forceinline__ void mma16816(float* c, const uint32_t* a,
                                         uint32_t b0, uint32_t b1) {
    asm volatile(
        "mma.sync.aligned.m16n8k16.row.col.f32.bf16.bf16.f32 "
        "{%0,%1,%2,%3}, {%4,%5,%6,%7}, {%8,%9}, {%0,%1,%2,%3};"
        : "+f"(c[0]), "+f"(c[1]), "+f"(c[2]), "+f"(c[3])
        : "r"(a[0]), "r"(a[1]), "r"(a[2]), "r"(a[3]), "r"(b0), "r"(b1));
}

// -------------------- pack: W_hh -> per-block [k][24] + zero ht -------------
__global__ void pack_kernel(const float* __restrict__ W_hh) {
    int o = blockIdx.x * blockDim.x + threadIdx.x;
    if (o < NBLK * D_SZ * 24) {
        int bx = o / (D_SZ * 24);
        int r  = o - bx * (D_SZ * 24);
        int k  = r / 24;
        int j  = r - k * 24;
        int g  = j >> 3, ci = j & 7;
        g_wtb[o] = W_hh[(size_t)k * G3 + g * H_SZ + bx * 8 + ci];
    }
    if (o < 2 * H_SZ * B_SZ) ((float*)g_ht)[o] = 0.0f;
}

// -------------------- convert A: X -> [xh | xl | xh] bf16 -------------------
__global__ void convA_kernel(const float* __restrict__ X) {
    int idx = blockIdx.x * blockDim.x + threadIdx.x;   // one float4 each
    float4 v = *(const float4*)(X + (size_t)idx * 4);
    int m  = idx >> 8;
    int k4 = (idx & 255) * 4;
    __nv_bfloat16 h0 = __float2bfloat16(v.x), h1 = __float2bfloat16(v.y);
    __nv_bfloat16 h2 = __float2bfloat16(v.z), h3 = __float2bfloat16(v.w);
    __nv_bfloat16 l0 = __float2bfloat16(v.x - __bfloat162float(h0));
    __nv_bfloat16 l1 = __float2bfloat16(v.y - __bfloat162float(h1));
    __nv_bfloat16 l2 = __float2bfloat16(v.z - __bfloat162float(h2));
    __nv_bfloat16 l3 = __float2bfloat16(v.w - __bfloat162float(h3));
    __nv_bfloat162 hA = {h0, h1}, hB = {h2, h3}, lA = {l0, l1}, lB = {l2, l3};
    uint2 hp = {*(unsigned*)&hA, *(unsigned*)&hB};
    uint2 lp = {*(unsigned*)&lA, *(unsigned*)&lB};
    __nv_bfloat16* base = g_aext + (size_t)m * KEXT + k4;
    *(uint2*)base = hp;
    *(uint2*)(base + D_SZ) = lp;
    *(uint2*)(base + 2 * D_SZ) = hp;
}

// -------------------- convert B: W_ih^T -> [wh ; wh ; wl] [n][k] bf16 -------
__global__ void convB_kernel(const float* __restrict__ W) {
    __shared__ float tile[32][33];
    int n0 = blockIdx.x * 32, k0 = blockIdx.y * 32;
    int tx = threadIdx.x, ty = threadIdx.y;
#pragma unroll
    for (int j = 0; j < 4; j++) {
        int r = ty * 4 + j;
        tile[r][tx] = W[(size_t)(k0 + r) * G3 + n0 + tx];
    }
    __syncthreads();
#pragma unroll
    for (int j = 0; j < 4; j++) {
        int nl = ty * 4 + j;
        float w = tile[tx][nl];
        __nv_bfloat16 hi = __float2bfloat16(w);
        __nv_bfloat16 lo = __float2bfloat16(w - __bfloat162float(hi));
        __nv_bfloat16* row = g_bext + (size_t)(n0 + nl) * KEXT + k0 + tx;
        row[0] = hi;
        row[D_SZ] = hi;
        row[2 * D_SZ] = lo;
    }
}

// -------------------- mma.sync GEMM: gi = A_ext @ B_ext^T + bias ------------
// 128x128 block tile, 8 warps (4m x 2n), warp tile 32x64.
// K chunks of 64 bf16, SW128-swizzled smem, cp.async double buffer.
#define SM_BUF 32768           // A(16KB) + B(16KB) per buffer
#define SM_TOTAL_G (2 * SM_BUF)

__device__ __forceinline__ void gg_load(const __nv_bfloat16* Ab,
                                        const __nv_bfloat16* Bb,
                                        int c, uint32_t sb, int buf, int tid) {
    size_t koff = (size_t)c * 64;
    uint32_t base = sb + buf * SM_BUF;
#pragma unroll
    for (int i = 0; i < 4; i++) {
        int idx = tid + i * 256;            // 0..1023 float4 slots
        int row = idx >> 3, f4 = idx & 7;
        uint32_t sw = SW128((uint32_t)(row * 128 + f4 * 16));
        cp16(base + sw, Ab + (size_t)row * KEXT + koff + f4 * 8);
        cp16(base + 16384 + sw, Bb + (size_t)row * KEXT + koff + f4 * 8);
    }
    CP_COMMIT();
}

extern __shared__ unsigned char sm_gg[];
__global__ void __launch_bounds__(256, 2)
mmagemm_kernel(const float* __restrict__ bias) {
    uint32_t sb = smem_u32(sm_gg);
    int tid = threadIdx.x, wid = tid >> 5, lane = tid & 31;
    int n0 = blockIdx.x * 128, m0 = blockIdx.y * 128;
    int warp_m = wid & 3, warp_n = wid >> 2;

    // ldmatrix per-lane address constants (swizzle mask from row bits only)
    uint32_t Ca[2], Ma[2];
#pragma unroll
    for (int mi = 0; mi < 2; mi++) {
        int row = warp_m * 32 + mi * 16 + (lane & 15);
        Ca[mi] = (uint32_t)(row * 128 + (lane >> 4) * 16);
        Ma[mi] = (uint32_t)((row & 7) << 4);
    }
    uint32_t Cb[4], Mb[4];
#pragma unroll
    for (int np = 0; np < 4; np++) {
        int row = warp_n * 64 + np * 16 + (lane & 7) + ((lane >> 4) << 3);
        Cb[np] = (uint32_t)(row * 128 + ((lane >> 3) & 1) * 16);
        Mb[np] = (uint32_t)((row & 7) << 4);
    }

    float acc[2][8][4];
#pragma unroll
    for (int mi = 0; mi < 2; mi++)
#pragma unroll
        for (int ni = 0; ni < 8; ni++)
#pragma unroll
            for (int q = 0; q < 4; q++) acc[mi][ni][q] = 0.0f;

    const __nv_bfloat16* Ab = g_aext + (size_t)m0 * KEXT;
    const __nv_bfloat16* Bb = g_bext + (size_t)n0 * KEXT;

    gg_load(Ab, Bb, 0, sb, 0, tid);

    int buf = 0;
    for (int c = 0; c < NCHUNK; c++) {
        if (c + 1 < NCHUNK) {
            gg_load(Ab, Bb, c + 1, sb, buf ^ 1, tid);
            CP_WAIT(1);
        } else {
            CP_WAIT(0);
        }
        __syncthreads();

        uint32_t a_sm = sb + buf * SM_BUF;
        uint32_t b_sm = a_sm + 16384;
#pragma unroll
        for (int k16 = 0; k16 < 4; k16++) {
            uint32_t af[2][4], bf[4][4];
#pragma unroll
            for (int mi = 0; mi < 2; mi++)
                ldm_x4(af[mi], a_sm + ((Ca[mi] + k16 * 32) ^ Ma[mi]));
#pragma unroll
            for (int np = 0; np < 4; np++)
                ldm_x4(bf[np], b_sm + ((Cb[np] + k16 * 32) ^ Mb[np]));
#pragma unroll
            for (int mi = 0; mi < 2; mi++)
#pragma unroll
                for (int ni = 0; ni < 8; ni++)
                    mma16816(acc[mi][ni], af[mi],
                             bf[ni >> 1][(ni & 1) * 2],
                             bf[ni >> 1][(ni & 1) * 2 + 1]);
        }
        __syncthreads();
        buf ^= 1;
    }

    // epilogue: fragment layout rows lane>>2 (+8), cols (lane&3)*2 (+1)
    int r = lane >> 2, q = (lane & 3) * 2;
    int m_base = m0 + warp_m * 32;
    int n_base = n0 + warp_n * 64;
    float bv[8][2];
#pragma unroll
    for (int ni = 0; ni < 8; ni++) {
        bv[ni][0] = bias[n_base + ni * 8 + q];
        bv[ni][1] = bias[n_base + ni * 8 + q + 1];
    }
#pragma unroll
    for (int mi = 0; mi < 2; mi++) {
#pragma unroll
        for (int ni = 0; ni < 8; ni++) {
            float* p0 = g_gi + (size_t)(m_base + mi * 16 + r) * G3
                        + n_base + ni * 8 + q;
            float* p1 = p0 + 8 * G3;
            float2 v0 = {acc[mi][ni][0] + bv[ni][0], acc[mi][ni][1] + bv[ni][1]};
            float2 v1 = {acc[mi][ni][2] + bv[ni][0], acc[mi][ni][3] + bv[ni][1]};
            *(float2*)p0 = v0;
            *(float2*)p1 = v1;
        }
    }
}

// -------------------- grid barrier --------------------
__device__ __forceinline__ void grid_barrier() {
    __syncthreads();
    if (threadIdx.x == 0) {
        __threadfence();
        unsigned my = atomicAdd(&g_bar, 1u);
        unsigned target = my - (my % NBLK) + NBLK;
        unsigned v;
        do {
            asm volatile("ld.acquire.gpu.b32 %0, [%1];"
                         : "=r"(v) : "l"(&g_bar) : "memory");
            if ((int)(v - target) >= 0) break;
        } while (true);
    }
    __syncthreads();
}

// -------------------- persistent recurrent kernel (unchanged, known-good) ---
extern __shared__ unsigned char smem_raw[];
__global__ void __launch_bounds__(RTHREADS, 1)
rnn_kernel(const float* __restrict__ paddings, const float* __restrict__ b_hh,
           float* __restrict__ out, int out_size) {
    float* sw   = (float*)smem_raw;                    // [1024][24]  96KB
    u64*   sred = (u64*)(smem_raw + 98304);            // [8*12][32]  24KB
    float* sout = (float*)(smem_raw + 98304 + 24576);  // [32][9]

    int tid = threadIdx.x;
    int warp = tid >> 5, lane = tid & 31;
    int bx = blockIdx.x;
    int ci = tid >> 5;
    int b  = lane;
    int c  = bx * 8 + ci;

    {
        const float4* src = (const float4*)(g_wtb + (size_t)bx * D_SZ * 24);
        float4* dst = (float4*)sw;
#pragma unroll
        for (int i = 0; i < 24; i++) dst[i * RTHREADS + tid] = src[i * RTHREADS + tid];
    }
    float bh_r = b_hh[c], bh_z = b_hh[H_SZ + c], bh_n = b_hh[2 * H_SZ + c];
    __syncthreads();

    const bool has_tail =
        (size_t)out_size >= (size_t)T_STEPS * B_SZ * H_SZ + 2u * B_SZ * H_SZ;
    int kb = warp * 128;

    for (int t = 0; t < T_STEPS; t++) {
        const float* ht = g_ht[t & 1];
        size_t gm = (size_t)(t * B_SZ + b) * G3 + c;
        float ir  = __ldg(&g_gi[gm]);
        float iz  = __ldg(&g_gi[gm + H_SZ]);
        float in_ = __ldg(&g_gi[gm + 2 * H_SZ]);
        float p   = __ldg(&paddings[t * B_SZ + b]);
        float hp  = __ldcg(&ht[c * B_SZ + b]);

        u64 acc[12];
#pragma unroll
        for (int j = 0; j < 12; j++) acc[j] = 0ull;

        const float* hcol = ht + lane;
        float hbuf[8];
#pragma unroll
        for (int u = 0; u < 8; u++) hbuf[u] = __ldcg(hcol + (kb + u) * B_SZ);

        for (int kk = 0; kk < 128; kk += 8) {
            float hnx[8] = {0, 0, 0, 0, 0, 0, 0, 0};
            if (kk < 120) {
#pragma unroll
                for (int u = 0; u < 8; u++)
                    hnx[u] = __ldcg(hcol + (kb + kk + 8 + u) * B_SZ);
            }
#pragma unroll
            for (int u = 0; u < 8; u++) {
                int k = kb + kk + u;
                u64 h2 = dup2(hbuf[u]);
                const ulonglong2* wr = (const ulonglong2*)(sw + k * 24);
                ulonglong2 w0 = wr[0], w1 = wr[1], w2 = wr[2];
                ulonglong2 w3 = wr[3], w4 = wr[4], w5 = wr[5];
                acc[0]  = ffma2(h2, w0.x, acc[0]);
                acc[1]  = ffma2(h2, w0.y, acc[1]);
                acc[2]  = ffma2(h2, w1.x, acc[2]);
                acc[3]  = ffma2(h2, w1.y, acc[3]);
                acc[4]  = ffma2(h2, w2.x, acc[4]);
                acc[5]  = ffma2(h2, w2.y, acc[5]);
                acc[6]  = ffma2(h2, w3.x, acc[6]);
                acc[7]  = ffma2(h2, w3.y, acc[7]);
                acc[8]  = ffma2(h2, w4.x, acc[8]);
                acc[9]  = ffma2(h2, w4.y, acc[9]);
                acc[10] = ffma2(h2, w5.x, acc[10]);
                acc[11] = ffma2(h2, w5.y, acc[11]);
            }
#pragma unroll
            for (int u = 0; u < 8; u++) hbuf[u] = hnx[u];
        }

#pragma unroll
        for (int j = 0; j < 12; j++)
            sred[(warp * 12 + j) * B_SZ + lane] = acc[j];
        __syncthreads();

        int jr = ci >> 1;
        u64 pr = 0, pz = 0, pn = 0;
#pragma unroll
        for (int w = 0; w < 8; w++) {
            const u64* base = sred + (size_t)w * 12 * B_SZ;
            pr = addf2(pr, base[jr * B_SZ + b]);
            pz = addf2(pz, base[(4 + jr) * B_SZ + b]);
            pn = addf2(pn, base[(8 + jr) * B_SZ + b]);
        }
        int hi = ci & 1;
        float ar = (hi ? f2hi(pr) : f2lo(pr)) + bh_r;
        float az = (hi ? f2hi(pz) : f2lo(pz)) + bh_z;
        float an = (hi ? f2hi(pn) : f2lo(pn)) + bh_n;

        float r  = 1.0f / (1.0f + __expf(-(ir + ar)));
        float z  = 1.0f / (1.0f + __expf(-(iz + az)));
        float nn = tanhf(in_ + r * an);
        float hn = (1.0f - z) * nn + z * hp;
        hn = p * hp + (1.0f - p) * hn;

        g_ht[(t + 1) & 1][c * B_SZ + b] = hn;
        sout[b * 9 + ci] = hn;
        __syncthreads();

        {
            int b2 = tid >> 3, cl = tid & 7;
            float v = sout[b2 * 9 + cl];
            int cg = bx * 8 + cl;
            out[(size_t)t * B_SZ * H_SZ + b2 * H_SZ + cg] = v;
            if (t == T_STEPS - 1 && has_tail) {
                size_t tail = (size_t)T_STEPS * B_SZ * H_SZ;
                out[tail + b2 * H_SZ + cg] = v;
                out[tail + (size_t)B_SZ * H_SZ + b2 * H_SZ + cg] = v;
            }
        }
        grid_barrier();
    }
}

// -------------------- launch --------------------
extern "C" void kernel_launch(void* const* d_in, const int* in_sizes, int n_in,
                              void* d_out, int out_size) {
    const float* X        = (const float*)d_in[0];
    const float* paddings = (const float*)d_in[1];
    const float* W_ih     = (const float*)d_in[2];
    const float* W_hh     = (const float*)d_in[3];
    const float* b_ih     = (const float*)d_in[4];
    const float* b_hh     = (const float*)d_in[5];
    float* out = (float*)d_out;
    (void)in_sizes; (void)n_in;

    pack_kernel<<<(NBLK * D_SZ * 24 + 255) / 256, 256>>>(W_hh);

    convA_kernel<<<(T_STEPS * B_SZ * D_SZ / 4) / 256, 256>>>(X);
    convB_kernel<<<dim3(G3 / 32, D_SZ / 32), dim3(32, 8)>>>(W_ih);

    cudaFuncSetAttribute(mmagemm_kernel,
                         cudaFuncAttributeMaxDynamicSharedMemorySize, SM_TOTAL_G);
    mmagemm_kernel<<<dim3(G3 / 128, (T_STEPS * B_SZ) / 128), 256, SM_TOTAL_G>>>(b_ih);

    int smem_bytes = 98304 + 24576 + 32 * 9 * (int)sizeof(float);
    cudaFuncSetAttribute(rnn_kernel,
                         cudaFuncAttributeMaxDynamicSharedMemorySize, smem_bytes);
    rnn_kernel<<<NBLK, RTHREADS, smem_bytes>>>(paddings, b_hh, out, out_size);
}

// round 6
// speedup vs baseline: 3.0458x; 1.2299x over previous
#include <cuda_runtime.h>
#include <cuda_bf16.h>
#include <cstdint>

#define T_STEPS 512
#define B_SZ 32
#define D_SZ 1024
#define H_SZ 1024
#define G3 3072
#define KEXT 3072            // 3*D extended-K for bf16 split GEMM
#define NBLK 128
#define RTHREADS 256
#define NCHUNK (KEXT / 64)   // 48 K-chunks of 64 bf16

typedef unsigned long long u64;

// -------------------- device scratch --------------------
__device__ float g_gi[(size_t)T_STEPS * B_SZ * G3];             // [m][3072] fp32
__device__ __nv_bfloat16 g_aext[(size_t)T_STEPS * B_SZ * KEXT]; // [m][kext]
__device__ __nv_bfloat16 g_bext[(size_t)G3 * KEXT];             // [n][kext]
__device__ __nv_bfloat16 g_wt2[(size_t)NBLK * 65536];  // per-block smem image (Wh|Wl)
__device__ __nv_bfloat16 g_hext[2][B_SZ * 2048];       // h split: [b][hh(1024)|hl(1024)]
__device__ unsigned g_bar;

// -------------------- smem / mma helpers (base-target ISA only) -------------
__device__ __forceinline__ uint32_t smem_u32(const void* p) {
    uint32_t a;
    asm("{ .reg .u64 t; cvta.to.shared.u64 t, %1; cvt.u32.u64 %0, t; }"
        : "=r"(a) : "l"(p));
    return a;
}
#define SW128(off) ((off) ^ (((off) >> 3) & 0x70))

__device__ __forceinline__ void cp16(uint32_t sm, const void* g) {
    asm volatile("cp.async.cg.shared.global [%0], [%1], 16;" :: "r"(sm), "l"(g));
}
#define CP_COMMIT() asm volatile("cp.async.commit_group;" ::: "memory")
#define CP_WAIT(n)  asm volatile("cp.async.wait_group %0;" :: "n"(n) : "memory")

__device__ __forceinline__ void ldm_x4(uint32_t* r, uint32_t addr) {
    asm volatile("ldmatrix.sync.aligned.m8n8.x4.shared.b16 {%0,%1,%2,%3}, [%4];"
                 : "=r"(r[0]), "=r"(r[1]), "=r"(r[2]), "=r"(r[3]) : "r"(addr));
}
__device__ __forceinline__ void ldm_x2(uint32_t* r, uint32_t addr) {
    asm volatile("ldmatrix.sync.aligned.m8n8.x2.shared.b16 {%0,%1}, [%2];"
                 : "=r"(r[0]), "=r"(r[1]) : "r"(addr));
}
__device__ __forceinline__ void mma16816(float* c, const uint32_t* a,
                                         uint32_t b0, uint32_t b1) {
    asm volatile(
        "mma.sync.aligned.m16n8k16.row.col.f32.bf16.bf16.f32 "
        "{%0,%1,%2,%3}, {%4,%5,%6,%7}, {%8,%9}, {%0,%1,%2,%3};"
        : "+f"(c[0]), "+f"(c[1]), "+f"(c[2]), "+f"(c[3])
        : "r"(a[0]), "r"(a[1]), "r"(a[2]), "r"(a[3]), "r"(b0), "r"(b1));
}

// -------------------- pack: W_hh -> per-block swizzled bf16 split -----------
// smem image per block: Wh[32 rows pad][1024 k] + Wl same, XOR-swizzled:
// u16 idx(r,k) = (k>>4)*512 + r*16 + (((k>>3)&1 ^ (r>>2)&1)<<3) + (k&7)
__global__ void pack_kernel(const float* __restrict__ W_hh) {
    int o = blockIdx.x * blockDim.x + threadIdx.x;   // [k 1024][inner 4096]
    int k = o >> 12;
    int inner = o & 4095;
    float w = 0.0f;
    int r, bx;
    if (inner < 3072) {                 // coalesced read of W_hh row k
        int g = inner >> 10, rem = inner & 1023;
        bx = rem >> 3;
        r = g * 8 + (rem & 7);
        w = W_hh[(size_t)k * G3 + inner];
    } else {                            // zero pad rows 24..31
        int pi = inner - 3072;
        bx = pi & 127;
        r = 24 + (pi >> 7);
    }
    __nv_bfloat16 hi = __float2bfloat16(w);
    __nv_bfloat16 lo = __float2bfloat16(w - __bfloat162float(hi));
    int idx = (k >> 4) * 512 + r * 16 +
              (((((k >> 3) & 1) ^ ((r >> 2) & 1))) << 3) + (k & 7);
    size_t base = (size_t)bx * 65536;
    g_wt2[base + idx] = hi;
    g_wt2[base + 32768 + idx] = lo;
    if (o < 2 * B_SZ * 2048)
        ((__nv_bfloat16*)g_hext)[o] = __float2bfloat16(0.0f);
}

// -------------------- convert A: X -> [xh | xl | xh] bf16 -------------------
__global__ void convA_kernel(const float* __restrict__ X) {
    int idx = blockIdx.x * blockDim.x + threadIdx.x;   // one float4 each
    float4 v = *(const float4*)(X + (size_t)idx * 4);
    int m  = idx >> 8;
    int k4 = (idx & 255) * 4;
    __nv_bfloat16 h0 = __float2bfloat16(v.x), h1 = __float2bfloat16(v.y);
    __nv_bfloat16 h2 = __float2bfloat16(v.z), h3 = __float2bfloat16(v.w);
    __nv_bfloat16 l0 = __float2bfloat16(v.x - __bfloat162float(h0));
    __nv_bfloat16 l1 = __float2bfloat16(v.y - __bfloat162float(h1));
    __nv_bfloat16 l2 = __float2bfloat16(v.z - __bfloat162float(h2));
    __nv_bfloat16 l3 = __float2bfloat16(v.w - __bfloat162float(h3));
    __nv_bfloat162 hA = {h0, h1}, hB = {h2, h3}, lA = {l0, l1}, lB = {l2, l3};
    uint2 hp = {*(unsigned*)&hA, *(unsigned*)&hB};
    uint2 lp = {*(unsigned*)&lA, *(unsigned*)&lB};
    __nv_bfloat16* base = g_aext + (size_t)m * KEXT + k4;
    *(uint2*)base = hp;
    *(uint2*)(base + D_SZ) = lp;
    *(uint2*)(base + 2 * D_SZ) = hp;
}

// -------------------- convert B: W_ih^T -> [wh ; wh ; wl] [n][k] bf16 -------
__global__ void convB_kernel(const float* __restrict__ W) {
    __shared__ float tile[32][33];
    int n0 = blockIdx.x * 32, k0 = blockIdx.y * 32;
    int tx = threadIdx.x, ty = threadIdx.y;
#pragma unroll
    for (int j = 0; j < 4; j++) {
        int r = ty * 4 + j;
        tile[r][tx] = W[(size_t)(k0 + r) * G3 + n0 + tx];
    }
    __syncthreads();
#pragma unroll
    for (int j = 0; j < 4; j++) {
        int nl = ty * 4 + j;
        float w = tile[tx][nl];
        __nv_bfloat16 hi = __float2bfloat16(w);
        __nv_bfloat16 lo = __float2bfloat16(w - __bfloat162float(hi));
        __nv_bfloat16* row = g_bext + (size_t)(n0 + nl) * KEXT + k0 + tx;
        row[0] = hi;
        row[D_SZ] = hi;
        row[2 * D_SZ] = lo;
    }
}

// -------------------- mma.sync GEMM: gi = A_ext @ B_ext^T + bias (R5) -------
#define SM_BUF 32768
#define SM_TOTAL_G (2 * SM_BUF)

__device__ __forceinline__ void gg_load(const __nv_bfloat16* Ab,
                                        const __nv_bfloat16* Bb,
                                        int c, uint32_t sb, int buf, int tid) {
    size_t koff = (size_t)c * 64;
    uint32_t base = sb + buf * SM_BUF;
#pragma unroll
    for (int i = 0; i < 4; i++) {
        int idx = tid + i * 256;
        int row = idx >> 3, f4 = idx & 7;
        uint32_t sw = SW128((uint32_t)(row * 128 + f4 * 16));
        cp16(base + sw, Ab + (size_t)row * KEXT + koff + f4 * 8);
        cp16(base + 16384 + sw, Bb + (size_t)row * KEXT + koff + f4 * 8);
    }
    CP_COMMIT();
}

extern __shared__ unsigned char sm_gg[];
__global__ void __launch_bounds__(256, 2)
mmagemm_kernel(const float* __restrict__ bias) {
    uint32_t sb = smem_u32(sm_gg);
    int tid = threadIdx.x, wid = tid >> 5, lane = tid & 31;
    int n0 = blockIdx.x * 128, m0 = blockIdx.y * 128;
    int warp_m = wid & 3, warp_n = wid >> 2;

    uint32_t Ca[2], Ma[2];
#pragma unroll
    for (int mi = 0; mi < 2; mi++) {
        int row = warp_m * 32 + mi * 16 + (lane & 15);
        Ca[mi] = (uint32_t)(row * 128 + (lane >> 4) * 16);
        Ma[mi] = (uint32_t)((row & 7) << 4);
    }
    uint32_t Cb[4], Mb[4];
#pragma unroll
    for (int np = 0; np < 4; np++) {
        int row = warp_n * 64 + np * 16 + (lane & 7) + ((lane >> 4) << 3);
        Cb[np] = (uint32_t)(row * 128 + ((lane >> 3) & 1) * 16);
        Mb[np] = (uint32_t)((row & 7) << 4);
    }

    float acc[2][8][4];
#pragma unroll
    for (int mi = 0; mi < 2; mi++)
#pragma unroll
        for (int ni = 0; ni < 8; ni++)
#pragma unroll
            for (int q = 0; q < 4; q++) acc[mi][ni][q] = 0.0f;

    const __nv_bfloat16* Ab = g_aext + (size_t)m0 * KEXT;
    const __nv_bfloat16* Bb = g_bext + (size_t)n0 * KEXT;

    gg_load(Ab, Bb, 0, sb, 0, tid);

    int buf = 0;
    for (int c = 0; c < NCHUNK; c++) {
        if (c + 1 < NCHUNK) {
            gg_load(Ab, Bb, c + 1, sb, buf ^ 1, tid);
            CP_WAIT(1);
        } else {
            CP_WAIT(0);
        }
        __syncthreads();

        uint32_t a_sm = sb + buf * SM_BUF;
        uint32_t b_sm = a_sm + 16384;
#pragma unroll
        for (int k16 = 0; k16 < 4; k16++) {
            uint32_t af[2][4], bf[4][4];
#pragma unroll
            for (int mi = 0; mi < 2; mi++)
                ldm_x4(af[mi], a_sm + ((Ca[mi] + k16 * 32) ^ Ma[mi]));
#pragma unroll
            for (int np = 0; np < 4; np++)
                ldm_x4(bf[np], b_sm + ((Cb[np] + k16 * 32) ^ Mb[np]));
#pragma unroll
            for (int mi = 0; mi < 2; mi++)
#pragma unroll
                for (int ni = 0; ni < 8; ni++)
                    mma16816(acc[mi][ni], af[mi],
                             bf[ni >> 1][(ni & 1) * 2],
                             bf[ni >> 1][(ni & 1) * 2 + 1]);
        }
        __syncthreads();
        buf ^= 1;
    }

    int r = lane >> 2, q = (lane & 3) * 2;
    int m_base = m0 + warp_m * 32;
    int n_base = n0 + warp_n * 64;
    float bv[8][2];
#pragma unroll
    for (int ni = 0; ni < 8; ni++) {
        bv[ni][0] = bias[n_base + ni * 8 + q];
        bv[ni][1] = bias[n_base + ni * 8 + q + 1];
    }
#pragma unroll
    for (int mi = 0; mi < 2; mi++) {
#pragma unroll
        for (int ni = 0; ni < 8; ni++) {
            float* p0 = g_gi + (size_t)(m_base + mi * 16 + r) * G3
                        + n_base + ni * 8 + q;
            float* p1 = p0 + 8 * G3;
            float2 v0 = {acc[mi][ni][0] + bv[ni][0], acc[mi][ni][1] + bv[ni][1]};
            float2 v1 = {acc[mi][ni][2] + bv[ni][0], acc[mi][ni][3] + bv[ni][1]};
            *(float2*)p0 = v0;
            *(float2*)p1 = v1;
        }
    }
}

// -------------------- grid barrier --------------------
__device__ __forceinline__ void grid_barrier() {
    __syncthreads();
    if (threadIdx.x == 0) {
        __threadfence();
        unsigned my = atomicAdd(&g_bar, 1u);
        unsigned target = my - (my % NBLK) + NBLK;
        unsigned v;
        do {
            asm volatile("ld.acquire.gpu.b32 %0, [%1];"
                         : "=r"(v) : "l"(&g_bar) : "memory");
            if ((int)(v - target) >= 0) break;
        } while (true);
    }
    __syncthreads();
}

// -------------------- persistent recurrent kernel: tensor-core matvec -------
// 128 blocks x 256 thr. Block owns 24 gate-cols; weights (Wh|Wl) in SMEM.
// Warp w: k-slice [128w,128w+128): terms hh@Wh + hh@Wl + hl@Wh via mma.sync.
// Partials (fp32) reduced across 8 warps in SMEM; gate math thread = (ci,b);
// h_prev lives in a register (thread owns its (c,b)).
#define SRED_OFF 131072
#define SOUT_OFF (131072 + 25600)
#define RSM_TOTAL (SOUT_OFF + 1280)

extern __shared__ unsigned char rsm[];
__global__ void __launch_bounds__(RTHREADS, 1)
rnn_kernel(const float* __restrict__ paddings, const float* __restrict__ b_hh,
           float* __restrict__ out, int out_size) {
    float* sred = (float*)(rsm + SRED_OFF);   // [8 warps][24 n][33] fp32
    float* sout = (float*)(rsm + SOUT_OFF);   // [32][9]
    uint32_t sWb = smem_u32(rsm);             // Wh at +0, Wl at +65536 (bytes)

    int tid = threadIdx.x, wid = tid >> 5, lane = tid & 31;
    int bx = blockIdx.x;
    int ci = wid, b = lane;
    int c = bx * 8 + ci;

    // load pre-swizzled weights (128KB) once
    {
        const float4* src = (const float4*)(g_wt2 + (size_t)bx * 65536);
        float4* dst = (float4*)rsm;
#pragma unroll
        for (int i = 0; i < 32; i++) dst[i * RTHREADS + tid] = src[i * RTHREADS + tid];
    }
    float bh_r = b_hh[c], bh_z = b_hh[H_SZ + c], bh_n = b_hh[2 * H_SZ + c];
    float hreg = 0.0f;
    __syncthreads();

    // ldmatrix.x2 lane address pieces (lanes 16-31 mirror 0-15)
    int ll = lane & 15;
    int half = ll >> 3;
    // A-frag LDG lane pieces
    int ar = lane >> 2;            // row within m-tile
    int ac = (lane & 3) * 2;       // k-pair

    const bool has_tail =
        (size_t)out_size >= (size_t)T_STEPS * B_SZ * H_SZ + 2u * B_SZ * H_SZ;
    int kb = wid * 128;            // warp's k-slice base

    for (int t = 0; t < T_STEPS; t++) {
        const unsigned* hx = (const unsigned*)g_hext[t & 1];  // u32 = 2 bf16
        size_t gm = (size_t)(t * B_SZ + b) * G3 + c;
        float ir  = __ldg(&g_gi[gm]);
        float iz  = __ldg(&g_gi[gm + H_SZ]);
        float in_ = __ldg(&g_gi[gm + 2 * H_SZ]);
        float p   = __ldg(&paddings[t * B_SZ + b]);

        float acc1[2][3][4], acc2[2][3][4];
#pragma unroll
        for (int mt = 0; mt < 2; mt++)
#pragma unroll
            for (int nt = 0; nt < 3; nt++)
#pragma unroll
                for (int q = 0; q < 4; q++) { acc1[mt][nt][q] = 0.f; acc2[mt][nt][q] = 0.f; }

        // A fragments: Af[buf][0..7]=hh (2 m-tiles x 4), [8..15]=hl
        uint32_t Af[2][16];
        {
            int k = kb;            // k16 = 0
#pragma unroll
            for (int mt = 0; mt < 2; mt++) {
                int i0 = (mt * 16 + ar) * 1024 + ((k + ac) >> 1);
                Af[0][mt * 4 + 0] = __ldcg(hx + i0);
                Af[0][mt * 4 + 1] = __ldcg(hx + i0 + 8192);
                Af[0][mt * 4 + 2] = __ldcg(hx + i0 + 4);
                Af[0][mt * 4 + 3] = __ldcg(hx + i0 + 8192 + 4);
                Af[0][8 + mt * 4 + 0] = __ldcg(hx + i0 + 512);
                Af[0][8 + mt * 4 + 1] = __ldcg(hx + i0 + 8192 + 512);
                Af[0][8 + mt * 4 + 2] = __ldcg(hx + i0 + 512 + 4);
                Af[0][8 + mt * 4 + 3] = __ldcg(hx + i0 + 8192 + 512 + 4);
            }
        }

        int cur = 0;
#pragma unroll
        for (int k16 = 0; k16 < 8; k16++) {
            // B fragments for this k16 (Wh and Wl)
            int k16g = wid * 8 + k16;
            uint32_t Wh[3][2], Wl[3][2];
#pragma unroll
            for (int nt = 0; nt < 3; nt++) {
                int n = nt * 8 + (ll & 7);
                uint32_t off = (uint32_t)(k16g * 1024 + n * 32 +
                               ((half ^ ((n >> 2) & 1)) << 4));
                ldm_x2(Wh[nt], sWb + off);
                ldm_x2(Wl[nt], sWb + 65536 + off);
            }
            // prefetch next k16 A-frags
            if (k16 < 7) {
                int k = kb + (k16 + 1) * 16;
#pragma unroll
                for (int mt = 0; mt < 2; mt++) {
                    int i0 = (mt * 16 + ar) * 1024 + ((k + ac) >> 1);
                    Af[cur ^ 1][mt * 4 + 0] = __ldcg(hx + i0);
                    Af[cur ^ 1][mt * 4 + 1] = __ldcg(hx + i0 + 8192);
                    Af[cur ^ 1][mt * 4 + 2] = __ldcg(hx + i0 + 4);
                    Af[cur ^ 1][mt * 4 + 3] = __ldcg(hx + i0 + 8192 + 4);
                    Af[cur ^ 1][8 + mt * 4 + 0] = __ldcg(hx + i0 + 512);
                    Af[cur ^ 1][8 + mt * 4 + 1] = __ldcg(hx + i0 + 8192 + 512);
                    Af[cur ^ 1][8 + mt * 4 + 2] = __ldcg(hx + i0 + 512 + 4);
                    Af[cur ^ 1][8 + mt * 4 + 3] = __ldcg(hx + i0 + 8192 + 512 + 4);
                }
            }
#pragma unroll
            for (int mt = 0; mt < 2; mt++)
#pragma unroll
                for (int nt = 0; nt < 3; nt++) {
                    mma16816(acc1[mt][nt], &Af[cur][mt * 4], Wh[nt][0], Wh[nt][1]);
                    mma16816(acc2[mt][nt], &Af[cur][mt * 4], Wl[nt][0], Wl[nt][1]);
                    mma16816(acc1[mt][nt], &Af[cur][8 + mt * 4], Wh[nt][0], Wh[nt][1]);
                }
            cur ^= 1;
        }

        // store partials: sred[(wid*24 + n)*33 + m]
#pragma unroll
        for (int mt = 0; mt < 2; mt++)
#pragma unroll
            for (int nt = 0; nt < 3; nt++)
#pragma unroll
                for (int q = 0; q < 4; q++) {
                    int m = mt * 16 + (lane >> 2) + ((q >> 1) << 3);
                    int n = nt * 8 + (lane & 3) * 2 + (q & 1);
                    sred[(wid * 24 + n) * 33 + m] = acc1[mt][nt][q] + acc2[mt][nt][q];
                }
        __syncthreads();

        // reduce 8 warps + gate math: thread = (ci, b)
        float ga = bh_r, gz = bh_z, gn = bh_n;
#pragma unroll
        for (int w = 0; w < 8; w++) {
            const float* bw = sred + w * 24 * 33;
            ga += bw[(0 + ci) * 33 + b];
            gz += bw[(8 + ci) * 33 + b];
            gn += bw[(16 + ci) * 33 + b];
        }
        float rg = 1.0f / (1.0f + __expf(-(ir + ga)));
        float zg = 1.0f / (1.0f + __expf(-(iz + gz)));
        float nn = tanhf(in_ + rg * gn);
        float hn = (1.0f - zg) * nn + zg * hreg;
        hn = p * hreg + (1.0f - p) * hn;
        hreg = hn;
        sout[b * 9 + ci] = hn;
        __syncthreads();

        // writers: out + split-bf16 publish of h
        {
            int b2 = tid >> 3, cl = tid & 7;
            float v = sout[b2 * 9 + cl];
            int cg = bx * 8 + cl;
            out[(size_t)t * B_SZ * H_SZ + b2 * H_SZ + cg] = v;
            __nv_bfloat16 hh = __float2bfloat16(v);
            __nv_bfloat16 hl = __float2bfloat16(v - __bfloat162float(hh));
            __nv_bfloat16* hnx = g_hext[(t + 1) & 1];
            hnx[b2 * 2048 + cg] = hh;
            hnx[b2 * 2048 + 1024 + cg] = hl;
            if (t == T_STEPS - 1 && has_tail) {
                size_t tail = (size_t)T_STEPS * B_SZ * H_SZ;
                out[tail + b2 * H_SZ + cg] = v;
                out[tail + (size_t)B_SZ * H_SZ + b2 * H_SZ + cg] = v;
            }
        }
        grid_barrier();
    }
}

// -------------------- launch --------------------
extern "C" void kernel_launch(void* const* d_in, const int* in_sizes, int n_in,
                              void* d_out, int out_size) {
    const float* X        = (const float*)d_in[0];
    const float* paddings = (const float*)d_in[1];
    const float* W_ih     = (const float*)d_in[2];
    const float* W_hh     = (const float*)d_in[3];
    const float* b_ih     = (const float*)d_in[4];
    const float* b_hh     = (const float*)d_in[5];
    float* out = (float*)d_out;
    (void)in_sizes; (void)n_in;

    pack_kernel<<<(D_SZ * 4096) / 256, 256>>>(W_hh);

    convA_kernel<<<(T_STEPS * B_SZ * D_SZ / 4) / 256, 256>>>(X);
    convB_kernel<<<dim3(G3 / 32, D_SZ / 32), dim3(32, 8)>>>(W_ih);

    cudaFuncSetAttribute(mmagemm_kernel,
                         cudaFuncAttributeMaxDynamicSharedMemorySize, SM_TOTAL_G);
    mmagemm_kernel<<<dim3(G3 / 128, (T_STEPS * B_SZ) / 128), 256, SM_TOTAL_G>>>(b_ih);

    cudaFuncSetAttribute(rnn_kernel,
                         cudaFuncAttributeMaxDynamicSharedMemorySize, RSM_TOTAL);
    rnn_kernel<<<NBLK, RTHREADS, RSM_TOTAL>>>(paddings, b_hh, out, out_size);
}